// round 4
// baseline (speedup 1.0000x reference)
#include <cuda_runtime.h>
#include <cstdint>

#define BSZ  32
#define SEQL 64
#define HID  256

// scratch (no cudaMalloc allowed)
__device__ float g_context[BSZ * HID];

// ---------- helpers ----------
__device__ __forceinline__ uint32_t s2u(const void* p) {
    uint32_t a;
    asm("{ .reg .u64 t; cvta.to.shared.u64 t, %1; cvt.u32.u64 %0, t; }" : "=r"(a) : "l"(p));
    return a;
}
__device__ __forceinline__ void ffma2(unsigned long long& d, unsigned long long a, unsigned long long b) {
    asm("fma.rn.f32x2 %0, %1, %2, %3;" : "=l"(d) : "l"(a), "l"(b), "l"(d));
}
__device__ __forceinline__ unsigned long long pk2(float a, float b) {
    unsigned long long r;
    asm("mov.b64 %0, {%1, %2};" : "=l"(r) : "f"(a), "f"(b));
    return r;
}
__device__ __forceinline__ float2 upk2(unsigned long long v) {
    float2 f;
    asm("mov.b64 {%0, %1}, %2;" : "=f"(f.x), "=f"(f.y) : "l"(v));
    return f;
}
__device__ __forceinline__ float sigf(float x)      { return __fdividef(1.0f, 1.0f + __expf(-x)); }
__device__ __forceinline__ float tanh_fast(float x) { return 1.0f - __fdividef(2.0f, __expf(2.0f * x) + 1.0f); }

// ============================================================================
// K1: context[b][h] = sum_s softmax_s(x[b]@Wa_x)[s,h] * x[b,s,h]
// grid 128 = (b:32) x (hchunk:4), 256 threads   (unchanged — verified)
// ============================================================================
__global__ void __launch_bounds__(256) k_context(const float* __restrict__ x,
                                                 const float* __restrict__ Wa) {
    __shared__ __align__(16) float xt[64][65];
    __shared__ __align__(16) float wt_sc[64][64];

    const int b   = blockIdx.x >> 2;
    const int hc  = blockIdx.x & 3;
    const int tid = threadIdx.x;
    const int h4  = tid & 15;
    const int s4  = tid >> 4;
    const float* xb = x + b * SEQL * HID;

    float acc[4][4];
#pragma unroll
    for (int i = 0; i < 4; i++)
#pragma unroll
        for (int j = 0; j < 4; j++) acc[i][j] = 0.0f;

    for (int kt = 0; kt < 4; ++kt) {
#pragma unroll
        for (int it = 0; it < 16; ++it) {
            int i = it * 256 + tid;
            int s = i >> 6, kk = i & 63;
            xt[kk][s] = xb[s * HID + kt * 64 + kk];
        }
#pragma unroll
        for (int it = 0; it < 16; ++it) {
            int i = it * 256 + tid;
            int kk = i >> 6, hl = i & 63;
            wt_sc[kk][hl] = Wa[(kt * 64 + kk) * HID + hc * 64 + hl];
        }
        __syncthreads();
#pragma unroll 4
        for (int kk = 0; kk < 64; ++kk) {
            float a0 = xt[kk][s4 * 4 + 0];
            float a1 = xt[kk][s4 * 4 + 1];
            float a2 = xt[kk][s4 * 4 + 2];
            float a3 = xt[kk][s4 * 4 + 3];
            float4 wv = *reinterpret_cast<const float4*>(&wt_sc[kk][h4 * 4]);
            acc[0][0] += a0 * wv.x; acc[0][1] += a0 * wv.y; acc[0][2] += a0 * wv.z; acc[0][3] += a0 * wv.w;
            acc[1][0] += a1 * wv.x; acc[1][1] += a1 * wv.y; acc[1][2] += a1 * wv.z; acc[1][3] += a1 * wv.w;
            acc[2][0] += a2 * wv.x; acc[2][1] += a2 * wv.y; acc[2][2] += a2 * wv.z; acc[2][3] += a2 * wv.w;
            acc[3][0] += a3 * wv.x; acc[3][1] += a3 * wv.y; acc[3][2] += a3 * wv.z; acc[3][3] += a3 * wv.w;
        }
        __syncthreads();
    }

#pragma unroll
    for (int i = 0; i < 4; ++i) {
        *reinterpret_cast<float4*>(&wt_sc[s4 * 4 + i][h4 * 4]) =
            make_float4(acc[i][0], acc[i][1], acc[i][2], acc[i][3]);
    }
    __syncthreads();

    if (tid < 64) {
        const int h = tid;
        float m = -3.4e38f;
#pragma unroll 8
        for (int s = 0; s < 64; ++s) m = fmaxf(m, wt_sc[s][h]);
        float Z = 0.0f, C = 0.0f;
#pragma unroll 8
        for (int s = 0; s < 64; ++s) {
            float e = __expf(wt_sc[s][h] - m);
            Z += e;
            C += e * xb[s * HID + hc * 64 + h];
        }
        g_context[b * HID + hc * 64 + h] = C / Z;
    }
}

// ============================================================================
// K3: LSTM recurrence. 16 clusters x 8 CTAs, 2 batches/cluster.
// CTA rank r owns h in [r*32, r*32+32).
// thread = (hl: tid>>4, cp: (tid>>3)&1, kq: tid&7).
//   cp=0 -> gates i(col h),f(col 256+h); cp=1 -> gates g(col 512+h),o(col 768+h)
// Per step (NO __syncthreads):
//   FFMA2 matvec -> shfl_xor kq all-reduce -> +gbase -> shfl_xor(8) cp exchange
//   -> all-lane pointwise (lane's batch = cp, ct in regs)
//   -> 1 st.shared::cluster per lane (rank kq) -> barrier.cluster
// ============================================================================
__global__ void __cluster_dims__(8, 1, 1) __launch_bounds__(512, 1)
k_recur(const float* __restrict__ Wi, const float* __restrict__ Wh,
        const float* __restrict__ bias, const float* __restrict__ Wf,
        const float* __restrict__ bf, float* __restrict__ out) {
    __shared__ __align__(16) float htbuf[2][2][256];    // [buf][b2][k]
    __shared__ __align__(16) float ctx_s[2][256];
    __shared__ float red_s[16];

    const int tid = threadIdx.x;
    uint32_t rnk;
    asm("mov.u32 %0, %%cluster_ctarank;" : "=r"(rnk));
    const int r     = (int)rnk;
    const int cbase = (blockIdx.x >> 3) * 2;
    const int hl = tid >> 4;          // 0..31
    const int cp = (tid >> 3) & 1;    // 0..1
    const int kq = tid & 7;           // 0..7
    const int colA = (2 * cp) * 256 + r * 32 + hl;   // gate 2cp
    const int colB = colA + 256;                     // gate 2cp+1

    const uint32_t htb = s2u(&htbuf[0][0][0]);

    // ---- init: zero buffer 0, load context ----
    ((float*)htbuf)[tid] = 0.0f;
    { int b2 = tid >> 8, k = tid & 255;
      ctx_s[b2][k] = g_context[(cbase + b2) * HID + k]; }
    __syncthreads();

    // ---- gbase = bias + ctx @ Wi, distributed like the step matvec ----
    float gbA[2] = {0.f, 0.f}, gbB[2] = {0.f, 0.f};
#pragma unroll 8
    for (int k = kq * 32; k < kq * 32 + 32; ++k) {
        float w0 = __ldg(&Wi[k * 1024 + colA]);
        float w1 = __ldg(&Wi[k * 1024 + colB]);
        float c0 = ctx_s[0][k], c1 = ctx_s[1][k];
        gbA[0] += c0 * w0; gbB[0] += c0 * w1;
        gbA[1] += c1 * w0; gbB[1] += c1 * w1;
    }
#pragma unroll
    for (int off = 1; off < 8; off <<= 1) {
        gbA[0] += __shfl_xor_sync(0xffffffffu, gbA[0], off);
        gbB[0] += __shfl_xor_sync(0xffffffffu, gbB[0], off);
        gbA[1] += __shfl_xor_sync(0xffffffffu, gbA[1], off);
        gbB[1] += __shfl_xor_sync(0xffffffffu, gbB[1], off);
    }
    {
        float bA = __ldg(&bias[colA]);
        float bB = __ldg(&bias[colB]);
        gbA[0] += bA; gbA[1] += bA;
        gbB[0] += bB; gbB[1] += bB;
    }

    // ---- Wh slice -> registers (32 k x 2 cols as f32x2 pairs) ----
    unsigned long long wA[16], wB[16];
#pragma unroll
    for (int p = 0; p < 16; ++p) {
        int k = kq * 32 + 2 * p;
        wA[p] = pk2(__ldg(&Wh[k * 1024 + colA]), __ldg(&Wh[(k + 1) * 1024 + colA]));
        wB[p] = pk2(__ldg(&Wh[k * 1024 + colB]), __ldg(&Wh[(k + 1) * 1024 + colB]));
    }
    __syncthreads();
    asm volatile("barrier.cluster.arrive.aligned;" ::: "memory");
    asm volatile("barrier.cluster.wait.aligned;" ::: "memory");

    float ct = 0.0f;

    // ---- 64 recurrence steps ----
    for (int t = 0; t < 64; ++t) {
        // matvec over this lane's k-range for both batches
        float pA[2], pB[2];
        const uint32_t abase = htb + (uint32_t)((t & 1) * 2048 + kq * 128);
#pragma unroll
        for (int b2 = 0; b2 < 2; ++b2) {
            unsigned long long accA = 0ull, accB = 0ull;
            const uint32_t a = abase + (uint32_t)(b2 * 1024);
#pragma unroll
            for (int q = 0; q < 8; ++q) {
                unsigned long long hA, hB;
                asm volatile("ld.shared.v2.u64 {%0, %1}, [%2];"
                             : "=l"(hA), "=l"(hB) : "r"(a + (uint32_t)(q * 16)));
                ffma2(accA, wA[2 * q],     hA);
                ffma2(accA, wA[2 * q + 1], hB);
                ffma2(accB, wB[2 * q],     hA);
                ffma2(accB, wB[2 * q + 1], hB);
            }
            float2 fA = upk2(accA), fB = upk2(accB);
            pA[b2] = fA.x + fA.y;
            pB[b2] = fB.x + fB.y;
        }

        // all-reduce over the 8 kq lanes (butterfly -> identical in all lanes)
#pragma unroll
        for (int off = 1; off < 8; off <<= 1) {
            pA[0] += __shfl_xor_sync(0xffffffffu, pA[0], off);
            pB[0] += __shfl_xor_sync(0xffffffffu, pB[0], off);
            pA[1] += __shfl_xor_sync(0xffffffffu, pA[1], off);
            pB[1] += __shfl_xor_sync(0xffffffffu, pB[1], off);
        }
        pA[0] += gbA[0]; pA[1] += gbA[1];
        pB[0] += gbB[0]; pB[1] += gbB[1];

        // exchange with opposite-cp lane (same hl, same kq)
        float qA0 = __shfl_xor_sync(0xffffffffu, pA[0], 8);
        float qA1 = __shfl_xor_sync(0xffffffffu, pA[1], 8);
        float qB0 = __shfl_xor_sync(0xffffffffu, pB[0], 8);
        float qB1 = __shfl_xor_sync(0xffffffffu, pB[1], 8);

        // this lane computes batch b = cp for hidden unit hl
        float gi = cp ? qA1 : pA[0];
        float gf = cp ? qB1 : pB[0];
        float gg = cp ? pA[1] : qA0;
        float go = cp ? pB[1] : qB0;

        float c  = sigf(gf) * ct + sigf(gi) * tanh_fast(gg);
        ct = c;
        float hv = sigf(go) * tanh_fast(c);

        // scatter: this lane stores ht[b=cp][r*32+hl] into rank kq's buffer
        {
            uint32_t wb    = (uint32_t)((t + 1) & 1);
            uint32_t laddr = htb + (wb * 512u + (uint32_t)cp * 256u
                                    + (uint32_t)(r * 32 + hl)) * 4u;
            uint32_t raddr;
            asm("mapa.shared::cluster.u32 %0, %1, %2;" : "=r"(raddr) : "r"(laddr), "r"(kq));
            asm volatile("st.shared::cluster.f32 [%0], %1;" :: "r"(raddr), "f"(hv));
        }
        asm volatile("barrier.cluster.arrive.aligned;" ::: "memory");
        asm volatile("barrier.cluster.wait.aligned;" ::: "memory");
    }

    // ---- epilogue: out[b] = ht @ Wf + bf (rank 0 only); final ht in buf 0 ----
    if (r == 0) {
        int b2 = tid >> 8, k = tid & 255;
        float v = htbuf[0][b2][k] * Wf[k];
#pragma unroll
        for (int off = 16; off > 0; off >>= 1) v += __shfl_xor_sync(0xffffffffu, v, off);
        if ((tid & 31) == 0) red_s[tid >> 5] = v;
        __syncthreads();
        if (tid == 0) {
            float o = bf[0];
#pragma unroll
            for (int w = 0; w < 8; ++w) o += red_s[w];
            out[cbase] = o;
        }
        if (tid == 256) {
            float o = bf[0];
#pragma unroll
            for (int w = 8; w < 16; ++w) o += red_s[w];
            out[cbase + 1] = o;
        }
    }
}

// ============================================================================
extern "C" void kernel_launch(void* const* d_in, const int* in_sizes, int n_in,
                              void* d_out, int out_size) {
    (void)in_sizes; (void)n_in; (void)out_size;
    const float* x    = (const float*)d_in[0];
    const float* Wa   = (const float*)d_in[1];
    // d_in[2] = ba : constant across seq, cancels inside softmax — unused
    const float* Wi   = (const float*)d_in[3];
    const float* Wh   = (const float*)d_in[4];
    const float* bias = (const float*)d_in[5];
    const float* Wf   = (const float*)d_in[6];
    const float* bf   = (const float*)d_in[7];
    float* out = (float*)d_out;

    k_context<<<128, 256>>>(x, Wa);
    k_recur<<<128, 512>>>(Wi, Wh, bias, Wf, bf, out);
}

// round 5
// speedup vs baseline: 1.0294x; 1.0294x over previous
#include <cuda_runtime.h>
#include <cstdint>

#define BSZ  32
#define SEQL 64
#define HID  256

// scratch (no cudaMalloc allowed)
__device__ float g_context[BSZ * HID];

// ---------- helpers ----------
__device__ __forceinline__ uint32_t s2u(const void* p) {
    uint32_t a;
    asm("{ .reg .u64 t; cvta.to.shared.u64 t, %1; cvt.u32.u64 %0, t; }" : "=r"(a) : "l"(p));
    return a;
}
__device__ __forceinline__ void ffma2(unsigned long long& d, unsigned long long a, unsigned long long b) {
    asm("fma.rn.f32x2 %0, %1, %2, %3;" : "=l"(d) : "l"(a), "l"(b), "l"(d));
}
__device__ __forceinline__ unsigned long long pk2(float a, float b) {
    unsigned long long r;
    asm("mov.b64 %0, {%1, %2};" : "=l"(r) : "f"(a), "f"(b));
    return r;
}
__device__ __forceinline__ float2 upk2(unsigned long long v) {
    float2 f;
    asm("mov.b64 {%0, %1}, %2;" : "=f"(f.x), "=f"(f.y) : "l"(v));
    return f;
}
__device__ __forceinline__ float tanh_mufu(float x) {
    float r;
    asm("tanh.approx.f32 %0, %1;" : "=f"(r) : "f"(x));
    return r;
}
__device__ __forceinline__ float sig_mufu(float x) {
    // sigmoid(x) = 0.5*tanh(x/2) + 0.5   (1 MUFU + 2 FMA)
    return fmaf(tanh_mufu(0.5f * x), 0.5f, 0.5f);
}

// ============================================================================
// K1: context[b][h] = sum_s softmax_s(x[b]@Wa_x)[s,h] * x[b,s,h]
// grid 128 = (b:32) x (hchunk:4), 256 threads   (unchanged — verified)
// ============================================================================
__global__ void __launch_bounds__(256) k_context(const float* __restrict__ x,
                                                 const float* __restrict__ Wa) {
    __shared__ __align__(16) float xt[64][65];
    __shared__ __align__(16) float wt_sc[64][64];

    const int b   = blockIdx.x >> 2;
    const int hc  = blockIdx.x & 3;
    const int tid = threadIdx.x;
    const int h4  = tid & 15;
    const int s4  = tid >> 4;
    const float* xb = x + b * SEQL * HID;

    float acc[4][4];
#pragma unroll
    for (int i = 0; i < 4; i++)
#pragma unroll
        for (int j = 0; j < 4; j++) acc[i][j] = 0.0f;

    for (int kt = 0; kt < 4; ++kt) {
#pragma unroll
        for (int it = 0; it < 16; ++it) {
            int i = it * 256 + tid;
            int s = i >> 6, kk = i & 63;
            xt[kk][s] = xb[s * HID + kt * 64 + kk];
        }
#pragma unroll
        for (int it = 0; it < 16; ++it) {
            int i = it * 256 + tid;
            int kk = i >> 6, hl = i & 63;
            wt_sc[kk][hl] = Wa[(kt * 64 + kk) * HID + hc * 64 + hl];
        }
        __syncthreads();
#pragma unroll 4
        for (int kk = 0; kk < 64; ++kk) {
            float a0 = xt[kk][s4 * 4 + 0];
            float a1 = xt[kk][s4 * 4 + 1];
            float a2 = xt[kk][s4 * 4 + 2];
            float a3 = xt[kk][s4 * 4 + 3];
            float4 wv = *reinterpret_cast<const float4*>(&wt_sc[kk][h4 * 4]);
            acc[0][0] += a0 * wv.x; acc[0][1] += a0 * wv.y; acc[0][2] += a0 * wv.z; acc[0][3] += a0 * wv.w;
            acc[1][0] += a1 * wv.x; acc[1][1] += a1 * wv.y; acc[1][2] += a1 * wv.z; acc[1][3] += a1 * wv.w;
            acc[2][0] += a2 * wv.x; acc[2][1] += a2 * wv.y; acc[2][2] += a2 * wv.z; acc[2][3] += a2 * wv.w;
            acc[3][0] += a3 * wv.x; acc[3][1] += a3 * wv.y; acc[3][2] += a3 * wv.z; acc[3][3] += a3 * wv.w;
        }
        __syncthreads();
    }

#pragma unroll
    for (int i = 0; i < 4; ++i) {
        *reinterpret_cast<float4*>(&wt_sc[s4 * 4 + i][h4 * 4]) =
            make_float4(acc[i][0], acc[i][1], acc[i][2], acc[i][3]);
    }
    __syncthreads();

    if (tid < 64) {
        const int h = tid;
        float m = -3.4e38f;
#pragma unroll 8
        for (int s = 0; s < 64; ++s) m = fmaxf(m, wt_sc[s][h]);
        float Z = 0.0f, C = 0.0f;
#pragma unroll 8
        for (int s = 0; s < 64; ++s) {
            float e = __expf(wt_sc[s][h] - m);
            Z += e;
            C += e * xb[s * HID + hc * 64 + h];
        }
        g_context[b * HID + hc * 64 + h] = C / Z;
    }
}

// ============================================================================
// K3: LSTM recurrence. 16 clusters x 8 CTAs, 2 batches/cluster.
// CTA rank r owns h in [r*32, r*32+32).
// thread = (hl: tid>>4, cp: (tid>>3)&1, kq: tid&7).
// Per step:
//   FFMA2 matvec -> shfl_xor kq all-reduce -> +gbase -> shfl_xor(8) cp exchange
//   -> all-lane pointwise via MUFU.TANH (lane's batch = cp, ct in regs)
//   -> kq==0 lanes STS hstage -> __syncthreads
//   -> WARP-UNIFORM remote store: warp w stores 32 floats to rank w>>1
//   -> barrier.cluster
// ============================================================================
__global__ void __cluster_dims__(8, 1, 1) __launch_bounds__(512, 1)
k_recur(const float* __restrict__ Wi, const float* __restrict__ Wh,
        const float* __restrict__ bias, const float* __restrict__ Wf,
        const float* __restrict__ bf, float* __restrict__ out) {
    __shared__ __align__(16) float htbuf[2][2][256];    // [buf][b2][k]
    __shared__ __align__(16) float ctx_s[2][256];
    __shared__ __align__(16) float hstage[2][32];       // [b2][hl] this CTA's new slice
    __shared__ float red_s[16];

    const int tid = threadIdx.x;
    uint32_t rnk;
    asm("mov.u32 %0, %%cluster_ctarank;" : "=r"(rnk));
    const int r     = (int)rnk;
    const int cbase = (blockIdx.x >> 3) * 2;
    const int hl = tid >> 4;          // 0..31
    const int cp = (tid >> 3) & 1;    // 0..1
    const int kq = tid & 7;           // 0..7
    const int colA = (2 * cp) * 256 + r * 32 + hl;   // gate 2cp
    const int colB = colA + 256;                     // gate 2cp+1

    // scatter role: warp w -> rank w>>1, batch w&1, element = lane
    const int wrp  = tid >> 5;
    const int lane = tid & 31;
    const int s_rank = wrp >> 1;
    const int s_b2   = wrp & 1;

    const uint32_t htb = s2u(&htbuf[0][0][0]);

    // ---- init: zero buffer 0, load context ----
    ((float*)htbuf)[tid] = 0.0f;
    { int b2 = tid >> 8, k = tid & 255;
      ctx_s[b2][k] = g_context[(cbase + b2) * HID + k]; }
    __syncthreads();

    // ---- gbase = bias + ctx @ Wi, distributed like the step matvec ----
    float gbA[2] = {0.f, 0.f}, gbB[2] = {0.f, 0.f};
#pragma unroll 8
    for (int k = kq * 32; k < kq * 32 + 32; ++k) {
        float w0 = __ldg(&Wi[k * 1024 + colA]);
        float w1 = __ldg(&Wi[k * 1024 + colB]);
        float c0 = ctx_s[0][k], c1 = ctx_s[1][k];
        gbA[0] += c0 * w0; gbB[0] += c0 * w1;
        gbA[1] += c1 * w0; gbB[1] += c1 * w1;
    }
#pragma unroll
    for (int off = 1; off < 8; off <<= 1) {
        gbA[0] += __shfl_xor_sync(0xffffffffu, gbA[0], off);
        gbB[0] += __shfl_xor_sync(0xffffffffu, gbB[0], off);
        gbA[1] += __shfl_xor_sync(0xffffffffu, gbA[1], off);
        gbB[1] += __shfl_xor_sync(0xffffffffu, gbB[1], off);
    }
    {
        float bA = __ldg(&bias[colA]);
        float bB = __ldg(&bias[colB]);
        gbA[0] += bA; gbA[1] += bA;
        gbB[0] += bB; gbB[1] += bB;
    }

    // ---- Wh slice -> registers (32 k x 2 cols as f32x2 pairs) ----
    unsigned long long wA[16], wB[16];
#pragma unroll
    for (int p = 0; p < 16; ++p) {
        int k = kq * 32 + 2 * p;
        wA[p] = pk2(__ldg(&Wh[k * 1024 + colA]), __ldg(&Wh[(k + 1) * 1024 + colA]));
        wB[p] = pk2(__ldg(&Wh[k * 1024 + colB]), __ldg(&Wh[(k + 1) * 1024 + colB]));
    }
    __syncthreads();
    asm volatile("barrier.cluster.arrive.aligned;" ::: "memory");
    asm volatile("barrier.cluster.wait.aligned;" ::: "memory");

    float ct = 0.0f;

    // ---- 64 recurrence steps ----
    for (int t = 0; t < 64; ++t) {
        // matvec over this lane's k-range for both batches
        float pA[2], pB[2];
        const uint32_t abase = htb + (uint32_t)((t & 1) * 2048 + kq * 128);
#pragma unroll
        for (int b2 = 0; b2 < 2; ++b2) {
            unsigned long long accA = 0ull, accB = 0ull;
            const uint32_t a = abase + (uint32_t)(b2 * 1024);
#pragma unroll
            for (int q = 0; q < 8; ++q) {
                unsigned long long hA, hB;
                asm volatile("ld.shared.v2.u64 {%0, %1}, [%2];"
                             : "=l"(hA), "=l"(hB) : "r"(a + (uint32_t)(q * 16)));
                ffma2(accA, wA[2 * q],     hA);
                ffma2(accA, wA[2 * q + 1], hB);
                ffma2(accB, wB[2 * q],     hA);
                ffma2(accB, wB[2 * q + 1], hB);
            }
            float2 fA = upk2(accA), fB = upk2(accB);
            pA[b2] = fA.x + fA.y;
            pB[b2] = fB.x + fB.y;
        }

        // all-reduce over the 8 kq lanes (butterfly -> identical in all lanes)
#pragma unroll
        for (int off = 1; off < 8; off <<= 1) {
            pA[0] += __shfl_xor_sync(0xffffffffu, pA[0], off);
            pB[0] += __shfl_xor_sync(0xffffffffu, pB[0], off);
            pA[1] += __shfl_xor_sync(0xffffffffu, pA[1], off);
            pB[1] += __shfl_xor_sync(0xffffffffu, pB[1], off);
        }
        pA[0] += gbA[0]; pA[1] += gbA[1];
        pB[0] += gbB[0]; pB[1] += gbB[1];

        // exchange with opposite-cp lane (same hl, same kq)
        float qA0 = __shfl_xor_sync(0xffffffffu, pA[0], 8);
        float qA1 = __shfl_xor_sync(0xffffffffu, pA[1], 8);
        float qB0 = __shfl_xor_sync(0xffffffffu, pB[0], 8);
        float qB1 = __shfl_xor_sync(0xffffffffu, pB[1], 8);

        // this lane computes batch b = cp for hidden unit hl
        float gi = cp ? qA1 : pA[0];
        float gf = cp ? qB1 : pB[0];
        float gg = cp ? pA[1] : qA0;
        float go = cp ? pB[1] : qB0;

        float c  = sig_mufu(gf) * ct + sig_mufu(gi) * tanh_mufu(gg);
        ct = c;
        float hv = sig_mufu(go) * tanh_mufu(c);

        // stage this CTA's new ht slice (kq==0 lanes hold each (cp,hl) once)
        if (kq == 0) hstage[cp][hl] = hv;
        __syncthreads();

        // warp-uniform remote scatter: warp w -> rank w>>1, batch w&1
        {
            float v = hstage[s_b2][lane];
            uint32_t wb    = (uint32_t)((t + 1) & 1);
            uint32_t laddr = htb + (wb * 512u + (uint32_t)s_b2 * 256u
                                    + (uint32_t)(r * 32 + lane)) * 4u;
            uint32_t raddr;
            asm("mapa.shared::cluster.u32 %0, %1, %2;" : "=r"(raddr) : "r"(laddr), "r"(s_rank));
            asm volatile("st.shared::cluster.f32 [%0], %1;" :: "r"(raddr), "f"(v));
        }
        asm volatile("barrier.cluster.arrive.aligned;" ::: "memory");
        asm volatile("barrier.cluster.wait.aligned;" ::: "memory");
    }

    // ---- epilogue: out[b] = ht @ Wf + bf (rank 0 only); final ht in buf 0 ----
    if (r == 0) {
        int b2 = tid >> 8, k = tid & 255;
        float v = htbuf[0][b2][k] * Wf[k];
#pragma unroll
        for (int off = 16; off > 0; off >>= 1) v += __shfl_xor_sync(0xffffffffu, v, off);
        if ((tid & 31) == 0) red_s[tid >> 5] = v;
        __syncthreads();
        if (tid == 0) {
            float o = bf[0];
#pragma unroll
            for (int w = 0; w < 8; ++w) o += red_s[w];
            out[cbase] = o;
        }
        if (tid == 256) {
            float o = bf[0];
#pragma unroll
            for (int w = 8; w < 16; ++w) o += red_s[w];
            out[cbase + 1] = o;
        }
    }
}

// ============================================================================
extern "C" void kernel_launch(void* const* d_in, const int* in_sizes, int n_in,
                              void* d_out, int out_size) {
    (void)in_sizes; (void)n_in; (void)out_size;
    const float* x    = (const float*)d_in[0];
    const float* Wa   = (const float*)d_in[1];
    // d_in[2] = ba : constant across seq, cancels inside softmax — unused
    const float* Wi   = (const float*)d_in[3];
    const float* Wh   = (const float*)d_in[4];
    const float* bias = (const float*)d_in[5];
    const float* Wf   = (const float*)d_in[6];
    const float* bf   = (const float*)d_in[7];
    float* out = (float*)d_out;

    k_context<<<128, 256>>>(x, Wa);
    k_recur<<<128, 512>>>(Wi, Wh, bias, Wf, bf, out);
}

// round 6
// speedup vs baseline: 3.1981x; 3.1069x over previous
#include <cuda_runtime.h>
#include <cstdint>

#define BSZ  32
#define SEQL 64
#define HID  256

// scratch (no cudaMalloc allowed)
__device__ float g_context[BSZ * HID];

// ---------- helpers ----------
__device__ __forceinline__ uint32_t s2u(const void* p) {
    uint32_t a;
    asm("{ .reg .u64 t; cvta.to.shared.u64 t, %1; cvt.u32.u64 %0, t; }" : "=r"(a) : "l"(p));
    return a;
}
__device__ __forceinline__ void ffma2(unsigned long long& d, unsigned long long a, unsigned long long b) {
    asm("fma.rn.f32x2 %0, %1, %2, %3;" : "=l"(d) : "l"(a), "l"(b), "l"(d));
}
__device__ __forceinline__ unsigned long long pk2(float a, float b) {
    unsigned long long r;
    asm("mov.b64 %0, {%1, %2};" : "=l"(r) : "f"(a), "f"(b));
    return r;
}
__device__ __forceinline__ float2 upk2(unsigned long long v) {
    float2 f;
    asm("mov.b64 {%0, %1}, %2;" : "=f"(f.x), "=f"(f.y) : "l"(v));
    return f;
}
__device__ __forceinline__ float tanh_mufu(float x) {
    float r;
    asm("tanh.approx.f32 %0, %1;" : "=f"(r) : "f"(x));
    return r;
}
__device__ __forceinline__ float sig_mufu(float x) {
    return fmaf(tanh_mufu(0.5f * x), 0.5f, 0.5f);
}

// ============================================================================
// K1: context[b][h] = sum_s softmax_s(x[b]@Wa_x)[s,h] * x[b,s,h]
// grid 128 = (b:32) x (hchunk:4), 256 threads   (unchanged — verified)
// ============================================================================
__global__ void __launch_bounds__(256) k_context(const float* __restrict__ x,
                                                 const float* __restrict__ Wa) {
    __shared__ __align__(16) float xt[64][65];
    __shared__ __align__(16) float wt_sc[64][64];

    const int b   = blockIdx.x >> 2;
    const int hc  = blockIdx.x & 3;
    const int tid = threadIdx.x;
    const int h4  = tid & 15;
    const int s4  = tid >> 4;
    const float* xb = x + b * SEQL * HID;

    float acc[4][4];
#pragma unroll
    for (int i = 0; i < 4; i++)
#pragma unroll
        for (int j = 0; j < 4; j++) acc[i][j] = 0.0f;

    for (int kt = 0; kt < 4; ++kt) {
#pragma unroll
        for (int it = 0; it < 16; ++it) {
            int i = it * 256 + tid;
            int s = i >> 6, kk = i & 63;
            xt[kk][s] = xb[s * HID + kt * 64 + kk];
        }
#pragma unroll
        for (int it = 0; it < 16; ++it) {
            int i = it * 256 + tid;
            int kk = i >> 6, hl = i & 63;
            wt_sc[kk][hl] = Wa[(kt * 64 + kk) * HID + hc * 64 + hl];
        }
        __syncthreads();
#pragma unroll 4
        for (int kk = 0; kk < 64; ++kk) {
            float a0 = xt[kk][s4 * 4 + 0];
            float a1 = xt[kk][s4 * 4 + 1];
            float a2 = xt[kk][s4 * 4 + 2];
            float a3 = xt[kk][s4 * 4 + 3];
            float4 wv = *reinterpret_cast<const float4*>(&wt_sc[kk][h4 * 4]);
            acc[0][0] += a0 * wv.x; acc[0][1] += a0 * wv.y; acc[0][2] += a0 * wv.z; acc[0][3] += a0 * wv.w;
            acc[1][0] += a1 * wv.x; acc[1][1] += a1 * wv.y; acc[1][2] += a1 * wv.z; acc[1][3] += a1 * wv.w;
            acc[2][0] += a2 * wv.x; acc[2][1] += a2 * wv.y; acc[2][2] += a2 * wv.z; acc[2][3] += a2 * wv.w;
            acc[3][0] += a3 * wv.x; acc[3][1] += a3 * wv.y; acc[3][2] += a3 * wv.z; acc[3][3] += a3 * wv.w;
        }
        __syncthreads();
    }

#pragma unroll
    for (int i = 0; i < 4; ++i) {
        *reinterpret_cast<float4*>(&wt_sc[s4 * 4 + i][h4 * 4]) =
            make_float4(acc[i][0], acc[i][1], acc[i][2], acc[i][3]);
    }
    __syncthreads();

    if (tid < 64) {
        const int h = tid;
        float m = -3.4e38f;
#pragma unroll 8
        for (int s = 0; s < 64; ++s) m = fmaxf(m, wt_sc[s][h]);
        float Z = 0.0f, C = 0.0f;
#pragma unroll 8
        for (int s = 0; s < 64; ++s) {
            float e = __expf(wt_sc[s][h] - m);
            Z += e;
            C += e * xb[s * HID + hc * 64 + h];
        }
        g_context[b * HID + hc * 64 + h] = C / Z;
    }
}

// ============================================================================
// K3: LSTM recurrence. 16 clusters x 8 CTAs, 2 batches/cluster.
// CTA rank r owns h in [r*32, r*32+32).
// thread = (hl: tid>>4, cp: (tid>>3)&1, kq: tid&7).
// ht in smem is PADDED per 32-float kq-block (stride 36 floats = 144B) so the
// 8 kq-lanes of each warp hit disjoint bank groups -> conflict-free LDS.
// Per step:
//   FFMA2 matvec (broadcast/conflict-free LDS) -> shfl kq all-reduce -> +gbase
//   -> shfl(8) cp exchange -> all-lane MUFU pointwise (ct in regs)
//   -> kq==0 STS hstage -> __syncthreads
//   -> warp-uniform remote store (warp w -> rank w>>1, 128B contiguous)
//   -> barrier.cluster
// ============================================================================
#define BLKF 36   // floats per kq block (32 data + 4 pad)

__global__ void __cluster_dims__(8, 1, 1) __launch_bounds__(512, 1)
k_recur(const float* __restrict__ Wi, const float* __restrict__ Wh,
        const float* __restrict__ bias, const float* __restrict__ Wf,
        const float* __restrict__ bf, float* __restrict__ out) {
    __shared__ __align__(16) float htbuf[2][2][8][BLKF];  // [buf][b2][kq][36]
    __shared__ __align__(16) float ctx_s[2][256];
    __shared__ __align__(16) float hstage[2][32];
    __shared__ float red_s[16];

    const int tid = threadIdx.x;
    uint32_t rnk;
    asm("mov.u32 %0, %%cluster_ctarank;" : "=r"(rnk));
    const int r     = (int)rnk;
    const int cbase = (blockIdx.x >> 3) * 2;
    const int hl = tid >> 4;          // 0..31
    const int cp = (tid >> 3) & 1;    // 0..1
    const int kq = tid & 7;           // 0..7
    const int colA = (2 * cp) * 256 + r * 32 + hl;   // gate 2cp
    const int colB = colA + 256;                     // gate 2cp+1

    // scatter role: warp w -> rank w>>1, batch w&1, element = lane
    const int wrp  = tid >> 5;
    const int lane = tid & 31;
    const int s_rank = wrp >> 1;
    const int s_b2   = wrp & 1;

    const uint32_t htb = s2u(&htbuf[0][0][0][0]);

    // ---- init: zero both buffers (incl. padding), load context ----
    for (int i = tid; i < 2 * 2 * 8 * BLKF; i += 512) ((float*)htbuf)[i] = 0.0f;
    { int b2 = tid >> 8, k = tid & 255;
      ctx_s[b2][k] = g_context[(cbase + b2) * HID + k]; }
    __syncthreads();

    // ---- gbase = bias + ctx @ Wi, distributed like the step matvec ----
    float gbA[2] = {0.f, 0.f}, gbB[2] = {0.f, 0.f};
#pragma unroll 8
    for (int k = kq * 32; k < kq * 32 + 32; ++k) {
        float w0 = __ldg(&Wi[k * 1024 + colA]);
        float w1 = __ldg(&Wi[k * 1024 + colB]);
        float c0 = ctx_s[0][k], c1 = ctx_s[1][k];
        gbA[0] += c0 * w0; gbB[0] += c0 * w1;
        gbA[1] += c1 * w0; gbB[1] += c1 * w1;
    }
#pragma unroll
    for (int off = 1; off < 8; off <<= 1) {
        gbA[0] += __shfl_xor_sync(0xffffffffu, gbA[0], off);
        gbB[0] += __shfl_xor_sync(0xffffffffu, gbB[0], off);
        gbA[1] += __shfl_xor_sync(0xffffffffu, gbA[1], off);
        gbB[1] += __shfl_xor_sync(0xffffffffu, gbB[1], off);
    }
    {
        float bA = __ldg(&bias[colA]);
        float bB = __ldg(&bias[colB]);
        gbA[0] += bA; gbA[1] += bA;
        gbB[0] += bB; gbB[1] += bB;
    }

    // ---- Wh slice -> registers (32 k x 2 cols as f32x2 pairs) ----
    unsigned long long wA[16], wB[16];
#pragma unroll
    for (int p = 0; p < 16; ++p) {
        int k = kq * 32 + 2 * p;
        wA[p] = pk2(__ldg(&Wh[k * 1024 + colA]), __ldg(&Wh[(k + 1) * 1024 + colA]));
        wB[p] = pk2(__ldg(&Wh[k * 1024 + colB]), __ldg(&Wh[(k + 1) * 1024 + colB]));
    }
    __syncthreads();
    asm volatile("barrier.cluster.arrive.aligned;" ::: "memory");
    asm volatile("barrier.cluster.wait.aligned;" ::: "memory");

    float ct = 0.0f;

    // ---- 64 recurrence steps ----
    for (int t = 0; t < 64; ++t) {
        // matvec over this lane's k-block for both batches (conflict-free)
        float pA[2], pB[2];
        const uint32_t bufb = htb + (uint32_t)((t & 1) * 2 * 8 * BLKF * 4);
#pragma unroll
        for (int b2 = 0; b2 < 2; ++b2) {
            unsigned long long accA = 0ull, accB = 0ull;
            const uint32_t a = bufb + (uint32_t)(((b2 * 8) + kq) * BLKF * 4);
#pragma unroll
            for (int q = 0; q < 8; ++q) {
                unsigned long long hA, hB;
                asm volatile("ld.shared.v2.u64 {%0, %1}, [%2];"
                             : "=l"(hA), "=l"(hB) : "r"(a + (uint32_t)(q * 16)));
                ffma2(accA, wA[2 * q],     hA);
                ffma2(accA, wA[2 * q + 1], hB);
                ffma2(accB, wB[2 * q],     hA);
                ffma2(accB, wB[2 * q + 1], hB);
            }
            float2 fA = upk2(accA), fB = upk2(accB);
            pA[b2] = fA.x + fA.y;
            pB[b2] = fB.x + fB.y;
        }

        // all-reduce over the 8 kq lanes
#pragma unroll
        for (int off = 1; off < 8; off <<= 1) {
            pA[0] += __shfl_xor_sync(0xffffffffu, pA[0], off);
            pB[0] += __shfl_xor_sync(0xffffffffu, pB[0], off);
            pA[1] += __shfl_xor_sync(0xffffffffu, pA[1], off);
            pB[1] += __shfl_xor_sync(0xffffffffu, pB[1], off);
        }
        pA[0] += gbA[0]; pA[1] += gbA[1];
        pB[0] += gbB[0]; pB[1] += gbB[1];

        // exchange with opposite-cp lane (same hl, same kq)
        float qA0 = __shfl_xor_sync(0xffffffffu, pA[0], 8);
        float qA1 = __shfl_xor_sync(0xffffffffu, pA[1], 8);
        float qB0 = __shfl_xor_sync(0xffffffffu, pB[0], 8);
        float qB1 = __shfl_xor_sync(0xffffffffu, pB[1], 8);

        // this lane computes batch b = cp for hidden unit hl
        float gi = cp ? qA1 : pA[0];
        float gf = cp ? qB1 : pB[0];
        float gg = cp ? pA[1] : qA0;
        float go = cp ? pB[1] : qB0;

        float c  = sig_mufu(gf) * ct + sig_mufu(gi) * tanh_mufu(gg);
        ct = c;
        float hv = sig_mufu(go) * tanh_mufu(c);

        // stage this CTA's new ht slice
        if (kq == 0) hstage[cp][hl] = hv;
        __syncthreads();

        // warp-uniform remote scatter: warp w -> rank w>>1, batch w&1.
        // Source CTA r's h-units are k-indices [r*32, r*32+32) = kq-block r.
        {
            float v = hstage[s_b2][lane];
            uint32_t wb    = (uint32_t)((t + 1) & 1);
            uint32_t laddr = htb + (uint32_t)((((wb * 2 + s_b2) * 8 + r) * BLKF + lane) * 4);
            uint32_t raddr;
            asm("mapa.shared::cluster.u32 %0, %1, %2;" : "=r"(raddr) : "r"(laddr), "r"(s_rank));
            asm volatile("st.shared::cluster.f32 [%0], %1;" :: "r"(raddr), "f"(v));
        }
        asm volatile("barrier.cluster.arrive.aligned;" ::: "memory");
        asm volatile("barrier.cluster.wait.aligned;" ::: "memory");
    }

    // ---- epilogue: out[b] = ht @ Wf + bf (rank 0 only); final ht in buf 0 ----
    if (r == 0) {
        int b2 = tid >> 8, k = tid & 255;
        float v = htbuf[0][b2][k >> 5][k & 31] * Wf[k];
#pragma unroll
        for (int off = 16; off > 0; off >>= 1) v += __shfl_xor_sync(0xffffffffu, v, off);
        if ((tid & 31) == 0) red_s[tid >> 5] = v;
        __syncthreads();
        if (tid == 0) {
            float o = bf[0];
#pragma unroll
            for (int w = 0; w < 8; ++w) o += red_s[w];
            out[cbase] = o;
        }
        if (tid == 256) {
            float o = bf[0];
#pragma unroll
            for (int w = 8; w < 16; ++w) o += red_s[w];
            out[cbase + 1] = o;
        }
    }
}

// ============================================================================
extern "C" void kernel_launch(void* const* d_in, const int* in_sizes, int n_in,
                              void* d_out, int out_size) {
    (void)in_sizes; (void)n_in; (void)out_size;
    const float* x    = (const float*)d_in[0];
    const float* Wa   = (const float*)d_in[1];
    // d_in[2] = ba : constant across seq, cancels inside softmax — unused
    const float* Wi   = (const float*)d_in[3];
    const float* Wh   = (const float*)d_in[4];
    const float* bias = (const float*)d_in[5];
    const float* Wf   = (const float*)d_in[6];
    const float* bf   = (const float*)d_in[7];
    float* out = (float*)d_out;

    k_context<<<128, 256>>>(x, Wa);
    k_recur<<<128, 512>>>(Wi, Wh, bias, Wf, bf, out);
}

// round 7
// speedup vs baseline: 3.7272x; 1.1654x over previous
#include <cuda_runtime.h>
#include <cstdint>

#define BSZ  32
#define SEQL 64
#define HID  256

// scratch (no cudaMalloc allowed)
__device__ float g_context[BSZ * HID];

// ---------- helpers ----------
__device__ __forceinline__ uint32_t s2u(const void* p) {
    uint32_t a;
    asm("{ .reg .u64 t; cvta.to.shared.u64 t, %1; cvt.u32.u64 %0, t; }" : "=r"(a) : "l"(p));
    return a;
}
__device__ __forceinline__ void ffma2(unsigned long long& d, unsigned long long a, unsigned long long b) {
    asm("fma.rn.f32x2 %0, %1, %2, %3;" : "=l"(d) : "l"(a), "l"(b), "l"(d));
}
__device__ __forceinline__ unsigned long long pk2(float a, float b) {
    unsigned long long r;
    asm("mov.b64 %0, {%1, %2};" : "=l"(r) : "f"(a), "f"(b));
    return r;
}
__device__ __forceinline__ float2 upk2(unsigned long long v) {
    float2 f;
    asm("mov.b64 {%0, %1}, %2;" : "=f"(f.x), "=f"(f.y) : "l"(v));
    return f;
}
__device__ __forceinline__ float tanh_mufu(float x) {
    float r;
    asm("tanh.approx.f32 %0, %1;" : "=f"(r) : "f"(x));
    return r;
}
__device__ __forceinline__ float sig_mufu(float x) {
    return fmaf(tanh_mufu(0.5f * x), 0.5f, 0.5f);
}
__device__ __forceinline__ void mbar_init(uint32_t addr, uint32_t cnt) {
    asm volatile("mbarrier.init.shared.b64 [%0], %1;" :: "r"(addr), "r"(cnt) : "memory");
}
__device__ __forceinline__ void mbar_arrive_expect(uint32_t addr, uint32_t tx) {
    asm volatile("mbarrier.arrive.expect_tx.shared.b64 _, [%0], %1;" :: "r"(addr), "r"(tx) : "memory");
}
__device__ __forceinline__ void mbar_wait(uint32_t addr, uint32_t parity) {
    asm volatile(
        "{\n\t"
        ".reg .pred P;\n\t"
        "WAIT_%=: \n\t"
        "mbarrier.try_wait.parity.acquire.cluster.shared::cta.b64 P, [%0], %1;\n\t"
        "@!P bra WAIT_%=;\n\t"
        "}"
        :: "r"(addr), "r"(parity) : "memory");
}
__device__ __forceinline__ void st_async_f32(uint32_t laddr, uint32_t lbar, float v, int rank) {
    uint32_t ra, rb;
    asm("mapa.shared::cluster.u32 %0, %1, %2;" : "=r"(ra) : "r"(laddr), "r"(rank));
    asm("mapa.shared::cluster.u32 %0, %1, %2;" : "=r"(rb) : "r"(lbar), "r"(rank));
    asm volatile("st.async.shared::cluster.mbarrier::complete_tx::bytes.f32 [%0], %1, [%2];"
                 :: "r"(ra), "f"(v), "r"(rb) : "memory");
}

// ============================================================================
// K1: context[b][h] = sum_s softmax_s(x[b]@Wa_x)[s,h] * x[b,s,h]
// grid 128 = (b:32) x (hchunk:4), 256 threads   (unchanged — verified)
// ============================================================================
__global__ void __launch_bounds__(256) k_context(const float* __restrict__ x,
                                                 const float* __restrict__ Wa) {
    __shared__ __align__(16) float xt[64][65];
    __shared__ __align__(16) float wt_sc[64][64];

    const int b   = blockIdx.x >> 2;
    const int hc  = blockIdx.x & 3;
    const int tid = threadIdx.x;
    const int h4  = tid & 15;
    const int s4  = tid >> 4;
    const float* xb = x + b * SEQL * HID;

    float acc[4][4];
#pragma unroll
    for (int i = 0; i < 4; i++)
#pragma unroll
        for (int j = 0; j < 4; j++) acc[i][j] = 0.0f;

    for (int kt = 0; kt < 4; ++kt) {
#pragma unroll
        for (int it = 0; it < 16; ++it) {
            int i = it * 256 + tid;
            int s = i >> 6, kk = i & 63;
            xt[kk][s] = xb[s * HID + kt * 64 + kk];
        }
#pragma unroll
        for (int it = 0; it < 16; ++it) {
            int i = it * 256 + tid;
            int kk = i >> 6, hl = i & 63;
            wt_sc[kk][hl] = Wa[(kt * 64 + kk) * HID + hc * 64 + hl];
        }
        __syncthreads();
#pragma unroll 4
        for (int kk = 0; kk < 64; ++kk) {
            float a0 = xt[kk][s4 * 4 + 0];
            float a1 = xt[kk][s4 * 4 + 1];
            float a2 = xt[kk][s4 * 4 + 2];
            float a3 = xt[kk][s4 * 4 + 3];
            float4 wv = *reinterpret_cast<const float4*>(&wt_sc[kk][h4 * 4]);
            acc[0][0] += a0 * wv.x; acc[0][1] += a0 * wv.y; acc[0][2] += a0 * wv.z; acc[0][3] += a0 * wv.w;
            acc[1][0] += a1 * wv.x; acc[1][1] += a1 * wv.y; acc[1][2] += a1 * wv.z; acc[1][3] += a1 * wv.w;
            acc[2][0] += a2 * wv.x; acc[2][1] += a2 * wv.y; acc[2][2] += a2 * wv.z; acc[2][3] += a2 * wv.w;
            acc[3][0] += a3 * wv.x; acc[3][1] += a3 * wv.y; acc[3][2] += a3 * wv.z; acc[3][3] += a3 * wv.w;
        }
        __syncthreads();
    }

#pragma unroll
    for (int i = 0; i < 4; ++i) {
        *reinterpret_cast<float4*>(&wt_sc[s4 * 4 + i][h4 * 4]) =
            make_float4(acc[i][0], acc[i][1], acc[i][2], acc[i][3]);
    }
    __syncthreads();

    if (tid < 64) {
        const int h = tid;
        float m = -3.4e38f;
#pragma unroll 8
        for (int s = 0; s < 64; ++s) m = fmaxf(m, wt_sc[s][h]);
        float Z = 0.0f, C = 0.0f;
#pragma unroll 8
        for (int s = 0; s < 64; ++s) {
            float e = __expf(wt_sc[s][h] - m);
            Z += e;
            C += e * xb[s * HID + hc * 64 + h];
        }
        g_context[b * HID + hc * 64 + h] = C / Z;
    }
}

// ============================================================================
// K3: LSTM recurrence. 16 clusters x 8 CTAs, 2 batches/cluster.
// CTA rank r owns h in [r*32, r*32+32).
// thread = (hl: tid>>4, cp: (tid>>3)&1, kq: tid&7).
// ht padded per 32-float kq-block (stride 36 floats) -> conflict-free LDS.
// Sync: NO barrier.cluster in the loop. Double-buffered tx-counting mbarriers:
//   consumer waits for 2048 bytes (full new ht) to land via st.async,
//   producers stream warp-uniform st.async (warp w -> rank w>>1) and never block.
// ============================================================================
#define BLKF 36   // floats per kq block (32 data + 4 pad)

__global__ void __cluster_dims__(8, 1, 1) __launch_bounds__(512, 1)
k_recur(const float* __restrict__ Wi, const float* __restrict__ Wh,
        const float* __restrict__ bias, const float* __restrict__ Wf,
        const float* __restrict__ bf, float* __restrict__ out) {
    __shared__ __align__(16) float htbuf[2][2][8][BLKF];  // [buf][b2][kq][36]
    __shared__ __align__(16) float ctx_s[2][256];
    __shared__ __align__(16) float hstage[2][32];
    __shared__ float red_s[16];
    __shared__ __align__(8) unsigned long long mbar[2];

    const int tid = threadIdx.x;
    uint32_t rnk;
    asm("mov.u32 %0, %%cluster_ctarank;" : "=r"(rnk));
    const int r     = (int)rnk;
    const int cbase = (blockIdx.x >> 3) * 2;
    const int hl = tid >> 4;          // 0..31
    const int cp = (tid >> 3) & 1;    // 0..1
    const int kq = tid & 7;           // 0..7
    const int colA = (2 * cp) * 256 + r * 32 + hl;   // gate 2cp
    const int colB = colA + 256;                     // gate 2cp+1

    // scatter role: warp w -> rank w>>1, batch w&1, element = lane
    const int wrp  = tid >> 5;
    const int lane = tid & 31;
    const int s_rank = wrp >> 1;
    const int s_b2   = wrp & 1;

    const uint32_t htb   = s2u(&htbuf[0][0][0][0]);
    const uint32_t mbarb = s2u(&mbar[0]);

    // ---- init: zero both buffers, load context, arm both mbarriers ----
    for (int i = tid; i < 2 * 2 * 8 * BLKF; i += 512) ((float*)htbuf)[i] = 0.0f;
    { int b2 = tid >> 8, k = tid & 255;
      ctx_s[b2][k] = g_context[(cbase + b2) * HID + k]; }
    if (tid == 0) {
        mbar_init(mbarb, 1);
        mbar_init(mbarb + 8, 1);
        mbar_arrive_expect(mbarb, 2048);
        mbar_arrive_expect(mbarb + 8, 2048);
    }
    __syncthreads();

    // ---- gbase = bias + ctx @ Wi, distributed like the step matvec ----
    float gbA[2] = {0.f, 0.f}, gbB[2] = {0.f, 0.f};
#pragma unroll 8
    for (int k = kq * 32; k < kq * 32 + 32; ++k) {
        float w0 = __ldg(&Wi[k * 1024 + colA]);
        float w1 = __ldg(&Wi[k * 1024 + colB]);
        float c0 = ctx_s[0][k], c1 = ctx_s[1][k];
        gbA[0] += c0 * w0; gbB[0] += c0 * w1;
        gbA[1] += c1 * w0; gbB[1] += c1 * w1;
    }
#pragma unroll
    for (int off = 1; off < 8; off <<= 1) {
        gbA[0] += __shfl_xor_sync(0xffffffffu, gbA[0], off);
        gbB[0] += __shfl_xor_sync(0xffffffffu, gbB[0], off);
        gbA[1] += __shfl_xor_sync(0xffffffffu, gbA[1], off);
        gbB[1] += __shfl_xor_sync(0xffffffffu, gbB[1], off);
    }
    {
        float bA = __ldg(&bias[colA]);
        float bB = __ldg(&bias[colB]);
        gbA[0] += bA; gbA[1] += bA;
        gbB[0] += bB; gbB[1] += bB;
    }

    // ---- Wh slice -> registers (32 k x 2 cols as f32x2 pairs) ----
    unsigned long long wA[16], wB[16];
#pragma unroll
    for (int p = 0; p < 16; ++p) {
        int k = kq * 32 + 2 * p;
        wA[p] = pk2(__ldg(&Wh[k * 1024 + colA]), __ldg(&Wh[(k + 1) * 1024 + colA]));
        wB[p] = pk2(__ldg(&Wh[k * 1024 + colB]), __ldg(&Wh[(k + 1) * 1024 + colB]));
    }
    __syncthreads();
    // one-time: all CTAs' mbarriers armed + zeroed ht visible before any st.async
    asm volatile("barrier.cluster.arrive.aligned;" ::: "memory");
    asm volatile("barrier.cluster.wait.aligned;" ::: "memory");

    float ct = 0.0f;

    // ---- 64 recurrence steps ----
    for (int t = 0; t < 64; ++t) {
        if (t > 0) {
            uint32_t ba = mbarb + (uint32_t)((t & 1) * 8);
            mbar_wait(ba, ((t - 1) >> 1) & 1);
            if (tid == 0) mbar_arrive_expect(ba, 2048);   // re-arm for step t+2
        }

        // matvec over this lane's k-block for both batches (conflict-free)
        float pA[2], pB[2];
        const uint32_t bufb = htb + (uint32_t)((t & 1) * 2 * 8 * BLKF * 4);
#pragma unroll
        for (int b2 = 0; b2 < 2; ++b2) {
            unsigned long long accA = 0ull, accB = 0ull;
            const uint32_t a = bufb + (uint32_t)(((b2 * 8) + kq) * BLKF * 4);
#pragma unroll
            for (int q = 0; q < 8; ++q) {
                unsigned long long hA, hB;
                asm volatile("ld.shared.v2.u64 {%0, %1}, [%2];"
                             : "=l"(hA), "=l"(hB) : "r"(a + (uint32_t)(q * 16)));
                ffma2(accA, wA[2 * q],     hA);
                ffma2(accA, wA[2 * q + 1], hB);
                ffma2(accB, wB[2 * q],     hA);
                ffma2(accB, wB[2 * q + 1], hB);
            }
            float2 fA = upk2(accA), fB = upk2(accB);
            pA[b2] = fA.x + fA.y;
            pB[b2] = fB.x + fB.y;
        }

        // all-reduce over the 8 kq lanes
#pragma unroll
        for (int off = 1; off < 8; off <<= 1) {
            pA[0] += __shfl_xor_sync(0xffffffffu, pA[0], off);
            pB[0] += __shfl_xor_sync(0xffffffffu, pB[0], off);
            pA[1] += __shfl_xor_sync(0xffffffffu, pA[1], off);
            pB[1] += __shfl_xor_sync(0xffffffffu, pB[1], off);
        }
        pA[0] += gbA[0]; pA[1] += gbA[1];
        pB[0] += gbB[0]; pB[1] += gbB[1];

        // exchange with opposite-cp lane (same hl, same kq)
        float qA0 = __shfl_xor_sync(0xffffffffu, pA[0], 8);
        float qA1 = __shfl_xor_sync(0xffffffffu, pA[1], 8);
        float qB0 = __shfl_xor_sync(0xffffffffu, pB[0], 8);
        float qB1 = __shfl_xor_sync(0xffffffffu, pB[1], 8);

        // this lane computes batch b = cp for hidden unit hl
        float gi = cp ? qA1 : pA[0];
        float gf = cp ? qB1 : pB[0];
        float gg = cp ? pA[1] : qA0;
        float go = cp ? pB[1] : qB0;

        float c  = sig_mufu(gf) * ct + sig_mufu(gi) * tanh_mufu(gg);
        ct = c;
        float hv = sig_mufu(go) * tanh_mufu(c);

        // stage this CTA's new ht slice
        if (kq == 0) hstage[cp][hl] = hv;
        __syncthreads();

        // warp-uniform async scatter: warp w -> rank w>>1, batch w&1.
        // Source CTA r's h-units are k-indices [r*32, r*32+32) = kq-block r.
        {
            float v = hstage[s_b2][lane];
            uint32_t wb    = (uint32_t)((t + 1) & 1);
            uint32_t laddr = htb + (uint32_t)((((wb * 2 + s_b2) * 8 + r) * BLKF + lane) * 4);
            uint32_t lbar  = mbarb + wb * 8u;
            st_async_f32(laddr, lbar, v, s_rank);
        }
        // no rendezvous: proceed to next step's wait
    }

    // final: last scatter (t=63) targeted buffer 0 / bar0 -> wait parity 1
    mbar_wait(mbarb, 1);

    // ---- epilogue: out[b] = ht @ Wf + bf (rank 0 only); final ht in buf 0 ----
    if (r == 0) {
        int b2 = tid >> 8, k = tid & 255;
        float v = htbuf[0][b2][k >> 5][k & 31] * Wf[k];
#pragma unroll
        for (int off = 16; off > 0; off >>= 1) v += __shfl_xor_sync(0xffffffffu, v, off);
        if ((tid & 31) == 0) red_s[tid >> 5] = v;
        __syncthreads();
        if (tid == 0) {
            float o = bf[0];
#pragma unroll
            for (int w = 0; w < 8; ++w) o += red_s[w];
            out[cbase] = o;
        }
        if (tid == 256) {
            float o = bf[0];
#pragma unroll
            for (int w = 8; w < 16; ++w) o += red_s[w];
            out[cbase + 1] = o;
        }
    }
    // keep the cluster alive until everyone is done reading peers' smem
    asm volatile("barrier.cluster.arrive.aligned;" ::: "memory");
    asm volatile("barrier.cluster.wait.aligned;" ::: "memory");
}

// ============================================================================
extern "C" void kernel_launch(void* const* d_in, const int* in_sizes, int n_in,
                              void* d_out, int out_size) {
    (void)in_sizes; (void)n_in; (void)out_size;
    const float* x    = (const float*)d_in[0];
    const float* Wa   = (const float*)d_in[1];
    // d_in[2] = ba : constant across seq, cancels inside softmax — unused
    const float* Wi   = (const float*)d_in[3];
    const float* Wh   = (const float*)d_in[4];
    const float* bias = (const float*)d_in[5];
    const float* Wf   = (const float*)d_in[6];
    const float* bf   = (const float*)d_in[7];
    float* out = (float*)d_out;

    k_context<<<128, 256>>>(x, Wa);
    k_recur<<<128, 512>>>(Wi, Wh, bias, Wf, bf, out);
}

// round 8
// speedup vs baseline: 3.7405x; 1.0036x over previous
#include <cuda_runtime.h>
#include <cstdint>

#define BSZ  32
#define SEQL 64
#define HID  256

// scratch (no cudaMalloc allowed)
__device__ float g_context[BSZ * HID];

// ---------- helpers ----------
__device__ __forceinline__ uint32_t s2u(const void* p) {
    uint32_t a;
    asm("{ .reg .u64 t; cvta.to.shared.u64 t, %1; cvt.u32.u64 %0, t; }" : "=r"(a) : "l"(p));
    return a;
}
__device__ __forceinline__ void ffma2(unsigned long long& d, unsigned long long a, unsigned long long b) {
    asm("fma.rn.f32x2 %0, %1, %2, %3;" : "=l"(d) : "l"(a), "l"(b), "l"(d));
}
__device__ __forceinline__ unsigned long long pk2(float a, float b) {
    unsigned long long r;
    asm("mov.b64 %0, {%1, %2};" : "=l"(r) : "f"(a), "f"(b));
    return r;
}
__device__ __forceinline__ float2 upk2(unsigned long long v) {
    float2 f;
    asm("mov.b64 {%0, %1}, %2;" : "=f"(f.x), "=f"(f.y) : "l"(v));
    return f;
}
__device__ __forceinline__ float tanh_mufu(float x) {
    float r;
    asm("tanh.approx.f32 %0, %1;" : "=f"(r) : "f"(x));
    return r;
}
__device__ __forceinline__ float sig_mufu(float x) {
    return fmaf(tanh_mufu(0.5f * x), 0.5f, 0.5f);
}
__device__ __forceinline__ void mbar_init(uint32_t addr, uint32_t cnt) {
    asm volatile("mbarrier.init.shared.b64 [%0], %1;" :: "r"(addr), "r"(cnt) : "memory");
}
__device__ __forceinline__ void mbar_arrive_expect(uint32_t addr, uint32_t tx) {
    asm volatile("mbarrier.arrive.expect_tx.shared.b64 _, [%0], %1;" :: "r"(addr), "r"(tx) : "memory");
}
// sleep-hint try_wait loop (HW TRYWAIT sleep, not spin-hammer)
__device__ __forceinline__ void mbar_wait(uint32_t addr, uint32_t parity) {
    asm volatile(
        "{\n\t"
        ".reg .pred P;\n\t"
        "WAIT_%=: \n\t"
        "mbarrier.try_wait.parity.acquire.cluster.shared::cta.b64 P, [%0], %1, 0x989680;\n\t"
        "@!P bra WAIT_%=;\n\t"
        "}"
        :: "r"(addr), "r"(parity) : "memory");
}
__device__ __forceinline__ void st_async_f32(uint32_t laddr, uint32_t lbar, float v, int rank) {
    uint32_t ra, rb;
    asm("mapa.shared::cluster.u32 %0, %1, %2;" : "=r"(ra) : "r"(laddr), "r"(rank));
    asm("mapa.shared::cluster.u32 %0, %1, %2;" : "=r"(rb) : "r"(lbar), "r"(rank));
    asm volatile("st.async.shared::cluster.mbarrier::complete_tx::bytes.f32 [%0], %1, [%2];"
                 :: "r"(ra), "f"(v), "r"(rb) : "memory");
}

// ============================================================================
// K1: context[b][h] = sum_s softmax_s(x[b]@Wa_x)[s,h] * x[b,s,h]
// grid 128 = (b:32) x (hchunk:4), 256 threads   (unchanged — verified)
// ============================================================================
__global__ void __launch_bounds__(256) k_context(const float* __restrict__ x,
                                                 const float* __restrict__ Wa) {
    __shared__ __align__(16) float xt[64][65];
    __shared__ __align__(16) float wt_sc[64][64];

    const int b   = blockIdx.x >> 2;
    const int hc  = blockIdx.x & 3;
    const int tid = threadIdx.x;
    const int h4  = tid & 15;
    const int s4  = tid >> 4;
    const float* xb = x + b * SEQL * HID;

    float acc[4][4];
#pragma unroll
    for (int i = 0; i < 4; i++)
#pragma unroll
        for (int j = 0; j < 4; j++) acc[i][j] = 0.0f;

    for (int kt = 0; kt < 4; ++kt) {
#pragma unroll
        for (int it = 0; it < 16; ++it) {
            int i = it * 256 + tid;
            int s = i >> 6, kk = i & 63;
            xt[kk][s] = xb[s * HID + kt * 64 + kk];
        }
#pragma unroll
        for (int it = 0; it < 16; ++it) {
            int i = it * 256 + tid;
            int kk = i >> 6, hl = i & 63;
            wt_sc[kk][hl] = Wa[(kt * 64 + kk) * HID + hc * 64 + hl];
        }
        __syncthreads();
#pragma unroll 4
        for (int kk = 0; kk < 64; ++kk) {
            float a0 = xt[kk][s4 * 4 + 0];
            float a1 = xt[kk][s4 * 4 + 1];
            float a2 = xt[kk][s4 * 4 + 2];
            float a3 = xt[kk][s4 * 4 + 3];
            float4 wv = *reinterpret_cast<const float4*>(&wt_sc[kk][h4 * 4]);
            acc[0][0] += a0 * wv.x; acc[0][1] += a0 * wv.y; acc[0][2] += a0 * wv.z; acc[0][3] += a0 * wv.w;
            acc[1][0] += a1 * wv.x; acc[1][1] += a1 * wv.y; acc[1][2] += a1 * wv.z; acc[1][3] += a1 * wv.w;
            acc[2][0] += a2 * wv.x; acc[2][1] += a2 * wv.y; acc[2][2] += a2 * wv.z; acc[2][3] += a2 * wv.w;
            acc[3][0] += a3 * wv.x; acc[3][1] += a3 * wv.y; acc[3][2] += a3 * wv.z; acc[3][3] += a3 * wv.w;
        }
        __syncthreads();
    }

#pragma unroll
    for (int i = 0; i < 4; ++i) {
        *reinterpret_cast<float4*>(&wt_sc[s4 * 4 + i][h4 * 4]) =
            make_float4(acc[i][0], acc[i][1], acc[i][2], acc[i][3]);
    }
    __syncthreads();

    if (tid < 64) {
        const int h = tid;
        float m = -3.4e38f;
#pragma unroll 8
        for (int s = 0; s < 64; ++s) m = fmaxf(m, wt_sc[s][h]);
        float Z = 0.0f, C = 0.0f;
#pragma unroll 8
        for (int s = 0; s < 64; ++s) {
            float e = __expf(wt_sc[s][h] - m);
            Z += e;
            C += e * xb[s * HID + hc * 64 + h];
        }
        g_context[b * HID + hc * 64 + h] = C / Z;
    }
}

// ============================================================================
// K3: LSTM recurrence. 16 clusters x 8 CTAs, 2 batches/cluster.
// CTA rank r owns h in [r*32, r*32+32).
// thread = (hl: tid>>4, cp: (tid>>3)&1, kq: tid&7).
// ht padded per 32-float kq-block (stride 36 floats) -> conflict-free LDS.
// Sync per step:
//   warp 0 ONLY waits on the tx-counting mbarrier (1792B from 7 remote ranks),
//   __syncthreads releases + orders; compute; stage; __syncthreads;
//   warp-uniform scatter: remote ranks via st.async, own rank via plain STS.
// ============================================================================
#define BLKF 36   // floats per kq block (32 data + 4 pad)

__global__ void __cluster_dims__(8, 1, 1) __launch_bounds__(512, 1)
k_recur(const float* __restrict__ Wi, const float* __restrict__ Wh,
        const float* __restrict__ bias, const float* __restrict__ Wf,
        const float* __restrict__ bf, float* __restrict__ out) {
    __shared__ __align__(16) float htbuf[2][2][8][BLKF];  // [buf][b2][kq][36]
    __shared__ __align__(16) float ctx_s[2][256];
    __shared__ __align__(16) float hstage[2][32];
    __shared__ float red_s[16];
    __shared__ __align__(8) unsigned long long mbar[2];

    const int tid = threadIdx.x;
    uint32_t rnk;
    asm("mov.u32 %0, %%cluster_ctarank;" : "=r"(rnk));
    const int r     = (int)rnk;
    const int cbase = (blockIdx.x >> 3) * 2;
    const int hl = tid >> 4;          // 0..31
    const int cp = (tid >> 3) & 1;    // 0..1
    const int kq = tid & 7;           // 0..7
    const int colA = (2 * cp) * 256 + r * 32 + hl;   // gate 2cp
    const int colB = colA + 256;                     // gate 2cp+1

    // scatter role: warp w -> rank w>>1, batch w&1, element = lane
    const int wrp  = tid >> 5;
    const int lane = tid & 31;
    const int s_rank = wrp >> 1;
    const int s_b2   = wrp & 1;

    const uint32_t htb   = s2u(&htbuf[0][0][0][0]);
    const uint32_t mbarb = s2u(&mbar[0]);

    // ---- init: zero both buffers, load context, arm both mbarriers ----
    for (int i = tid; i < 2 * 2 * 8 * BLKF; i += 512) ((float*)htbuf)[i] = 0.0f;
    { int b2 = tid >> 8, k = tid & 255;
      ctx_s[b2][k] = g_context[(cbase + b2) * HID + k]; }
    if (tid == 0) {
        mbar_init(mbarb, 1);
        mbar_init(mbarb + 8, 1);
        mbar_arrive_expect(mbarb, 1792);       // 7 remote ranks x 256B
        mbar_arrive_expect(mbarb + 8, 1792);
    }
    __syncthreads();

    // ---- gbase = bias + ctx @ Wi, distributed like the step matvec ----
    float gbA[2] = {0.f, 0.f}, gbB[2] = {0.f, 0.f};
#pragma unroll 8
    for (int k = kq * 32; k < kq * 32 + 32; ++k) {
        float w0 = __ldg(&Wi[k * 1024 + colA]);
        float w1 = __ldg(&Wi[k * 1024 + colB]);
        float c0 = ctx_s[0][k], c1 = ctx_s[1][k];
        gbA[0] += c0 * w0; gbB[0] += c0 * w1;
        gbA[1] += c1 * w0; gbB[1] += c1 * w1;
    }
#pragma unroll
    for (int off = 1; off < 8; off <<= 1) {
        gbA[0] += __shfl_xor_sync(0xffffffffu, gbA[0], off);
        gbB[0] += __shfl_xor_sync(0xffffffffu, gbB[0], off);
        gbA[1] += __shfl_xor_sync(0xffffffffu, gbA[1], off);
        gbB[1] += __shfl_xor_sync(0xffffffffu, gbB[1], off);
    }
    {
        float bA = __ldg(&bias[colA]);
        float bB = __ldg(&bias[colB]);
        gbA[0] += bA; gbA[1] += bA;
        gbB[0] += bB; gbB[1] += bB;
    }

    // ---- Wh slice -> registers (32 k x 2 cols as f32x2 pairs) ----
    unsigned long long wA[16], wB[16];
#pragma unroll
    for (int p = 0; p < 16; ++p) {
        int k = kq * 32 + 2 * p;
        wA[p] = pk2(__ldg(&Wh[k * 1024 + colA]), __ldg(&Wh[(k + 1) * 1024 + colA]));
        wB[p] = pk2(__ldg(&Wh[k * 1024 + colB]), __ldg(&Wh[(k + 1) * 1024 + colB]));
    }
    __syncthreads();
    // one-time: all CTAs' mbarriers armed + zeroed ht visible before any st.async
    asm volatile("barrier.cluster.arrive.aligned;" ::: "memory");
    asm volatile("barrier.cluster.wait.aligned;" ::: "memory");

    float ct = 0.0f;

    // ---- 64 recurrence steps ----
    for (int t = 0; t < 64; ++t) {
        if (t > 0) {
            // ELECT-ONE-WARP wait: warp 0 sleeps on the mbarrier; everyone
            // else parks at the bar (no 16-warp poll storm on the L1 port).
            uint32_t ba = mbarb + (uint32_t)((t & 1) * 8);
            if (wrp == 0) {
                mbar_wait(ba, ((t - 1) >> 1) & 1);
                if (lane == 0) mbar_arrive_expect(ba, 1792);  // re-arm for t+2
            }
            __syncthreads();   // releases + CTA-wide visibility of arrived data
        }

        // matvec over this lane's k-block for both batches (conflict-free)
        float pA[2], pB[2];
        const uint32_t bufb = htb + (uint32_t)((t & 1) * 2 * 8 * BLKF * 4);
#pragma unroll
        for (int b2 = 0; b2 < 2; ++b2) {
            unsigned long long accA = 0ull, accB = 0ull;
            const uint32_t a = bufb + (uint32_t)(((b2 * 8) + kq) * BLKF * 4);
#pragma unroll
            for (int q = 0; q < 8; ++q) {
                unsigned long long hA, hB;
                asm volatile("ld.shared.v2.u64 {%0, %1}, [%2];"
                             : "=l"(hA), "=l"(hB) : "r"(a + (uint32_t)(q * 16)));
                ffma2(accA, wA[2 * q],     hA);
                ffma2(accA, wA[2 * q + 1], hB);
                ffma2(accB, wB[2 * q],     hA);
                ffma2(accB, wB[2 * q + 1], hB);
            }
            float2 fA = upk2(accA), fB = upk2(accB);
            pA[b2] = fA.x + fA.y;
            pB[b2] = fB.x + fB.y;
        }

        // all-reduce over the 8 kq lanes
#pragma unroll
        for (int off = 1; off < 8; off <<= 1) {
            pA[0] += __shfl_xor_sync(0xffffffffu, pA[0], off);
            pB[0] += __shfl_xor_sync(0xffffffffu, pB[0], off);
            pA[1] += __shfl_xor_sync(0xffffffffu, pA[1], off);
            pB[1] += __shfl_xor_sync(0xffffffffu, pB[1], off);
        }
        pA[0] += gbA[0]; pA[1] += gbA[1];
        pB[0] += gbB[0]; pB[1] += gbB[1];

        // exchange with opposite-cp lane (same hl, same kq)
        float qA0 = __shfl_xor_sync(0xffffffffu, pA[0], 8);
        float qA1 = __shfl_xor_sync(0xffffffffu, pA[1], 8);
        float qB0 = __shfl_xor_sync(0xffffffffu, pB[0], 8);
        float qB1 = __shfl_xor_sync(0xffffffffu, pB[1], 8);

        // this lane computes batch b = cp for hidden unit hl
        float gi = cp ? qA1 : pA[0];
        float gf = cp ? qB1 : pB[0];
        float gg = cp ? pA[1] : qA0;
        float go = cp ? pB[1] : qB0;

        float c  = sig_mufu(gf) * ct + sig_mufu(gi) * tanh_mufu(gg);
        ct = c;
        float hv = sig_mufu(go) * tanh_mufu(c);

        // stage this CTA's new ht slice
        if (kq == 0) hstage[cp][hl] = hv;
        __syncthreads();

        // warp-uniform scatter: warp w -> rank w>>1, batch w&1.
        // Own rank: plain STS (ordered by next step's __syncthreads).
        // Remote ranks: st.async with tx accounting.
        {
            float v = hstage[s_b2][lane];
            uint32_t wb    = (uint32_t)((t + 1) & 1);
            uint32_t laddr = htb + (uint32_t)((((wb * 2 + s_b2) * 8 + r) * BLKF + lane) * 4);
            if (s_rank == r) {
                asm volatile("st.shared.f32 [%0], %1;" :: "r"(laddr), "f"(v) : "memory");
            } else {
                uint32_t lbar = mbarb + wb * 8u;
                st_async_f32(laddr, lbar, v, s_rank);
            }
        }
        // no rendezvous: proceed to next step's wait
    }

    // final: last scatter (t=63) targeted buffer 0 / bar0 -> wait parity 1
    if (wrp == 0) mbar_wait(mbarb, 1);
    __syncthreads();   // own-slice STS + remote data visible to all

    // ---- epilogue: out[b] = ht @ Wf + bf (rank 0 only); final ht in buf 0 ----
    if (r == 0) {
        int b2 = tid >> 8, k = tid & 255;
        float v = htbuf[0][b2][k >> 5][k & 31] * Wf[k];
#pragma unroll
        for (int off = 16; off > 0; off >>= 1) v += __shfl_xor_sync(0xffffffffu, v, off);
        if ((tid & 31) == 0) red_s[tid >> 5] = v;
        __syncthreads();
        if (tid == 0) {
            float o = bf[0];
#pragma unroll
            for (int w = 0; w < 8; ++w) o += red_s[w];
            out[cbase] = o;
        }
        if (tid == 256) {
            float o = bf[0];
#pragma unroll
            for (int w = 8; w < 16; ++w) o += red_s[w];
            out[cbase + 1] = o;
        }
    }
    // keep the cluster alive until everyone is done reading peers' smem
    asm volatile("barrier.cluster.arrive.aligned;" ::: "memory");
    asm volatile("barrier.cluster.wait.aligned;" ::: "memory");
}

// ============================================================================
extern "C" void kernel_launch(void* const* d_in, const int* in_sizes, int n_in,
                              void* d_out, int out_size) {
    (void)in_sizes; (void)n_in; (void)out_size;
    const float* x    = (const float*)d_in[0];
    const float* Wa   = (const float*)d_in[1];
    // d_in[2] = ba : constant across seq, cancels inside softmax — unused
    const float* Wi   = (const float*)d_in[3];
    const float* Wh   = (const float*)d_in[4];
    const float* bias = (const float*)d_in[5];
    const float* Wf   = (const float*)d_in[6];
    const float* bf   = (const float*)d_in[7];
    float* out = (float*)d_out;

    k_context<<<128, 256>>>(x, Wa);
    k_recur<<<128, 512>>>(Wi, Wh, bias, Wf, bf, out);
}